// round 14
// baseline (speedup 1.0000x reference)
#include <cuda_runtime.h>
#include <cuda_bf16.h>
#include <math.h>
#include <stdint.h>

#define BB 4
#define TT 2048
#define HH 4
#define DD 1024
#define PD 5120
#define BT (BB*TT)
#define BH 16

__device__ float g_P[(size_t)BT*PD], g_ACC[BT*DD], g_XSG[BT*HH], g_LAM[BH*TT];
__device__ int g_ctr;
__device__ __nv_bfloat16 g_XHI[BT*DD], g_XLO[BT*DD], g_WHI[(size_t)PD*DD], g_WLO[(size_t)PD*DD];
__device__ __nv_bfloat16 g_QHI[BT*DD], g_QLO[BT*DD], g_KHI[BT*DD], g_KLO[BT*DD];
__device__ __nv_bfloat16 g_EHI[BT*DD], g_ELO[BT*DD], g_ETHI[BT*DD], g_ETLO[BT*DD];
__device__ __nv_bfloat16 g_VTHI[BT*DD], g_VTLO[BT*DD];

__device__ __forceinline__ uint32_t smem_to_u32(const void* p) {
    uint32_t a;
    asm("{ .reg .u64 t; cvta.to.shared.u64 t, %1; cvt.u32.u64 %0, t; }" : "=r"(a) : "l"(p));
    return a;
}
#define CP_ASYNC16(d, s) asm volatile("cp.async.cg.shared.global [%0], [%1], 16;" :: "r"(d), "l"(s))
#define CP_COMMIT() asm volatile("cp.async.commit_group;" ::: "memory")
#define CP_WAIT0() asm volatile("cp.async.wait_group 0;" ::: "memory")
#define LDSM_X4(r, a) \
    asm volatile("ldmatrix.sync.aligned.m8n8.x4.shared.b16 {%0,%1,%2,%3}, [%4];" \
        : "=r"((r)[0]),"=r"((r)[1]),"=r"((r)[2]),"=r"((r)[3]) : "r"(a))
#define MMA_B16(c, a, b0, b1) \
    asm volatile("mma.sync.aligned.m16n8k16.row.col.f32.bf16.bf16.f32 " \
        "{%0,%1,%2,%3},{%4,%5,%6,%7},{%8,%9},{%0,%1,%2,%3};" \
        : "+f"((c)[0]),"+f"((c)[1]),"+f"((c)[2]),"+f"((c)[3]) \
        : "r"((a)[0]),"r"((a)[1]),"r"((a)[2]),"r"((a)[3]), "r"(b0),"r"(b1))
__device__ __forceinline__ void spl(float x, __nv_bfloat16& h, __nv_bfloat16& l) {
    h = __float2bfloat16(x); l = __float2bfloat16(x - __bfloat162float(h));
}
__device__ __forceinline__ uint32_t pkbf(__nv_bfloat16 a, __nv_bfloat16 b) {
    return (uint32_t)*(uint16_t*)&a | ((uint32_t)*(uint16_t*)&b << 16);
}

__global__ void splitx(const float* __restrict__ X, __nv_bfloat16* __restrict__ hi,
                       __nv_bfloat16* __restrict__ lo)
{
    const int i = blockIdx.x * 256 + threadIdx.x;
    float4 v = *(const float4*)(X + (size_t)i * 4);
    __nv_bfloat16 h[4], l[4];
    float vv[4] = {v.x, v.y, v.z, v.w};
#pragma unroll
    for (int j = 0; j < 4; j++) spl(vv[j], h[j], l[j]);
    *(uint2*)(hi + (size_t)i * 4) = *(uint2*)h;
    *(uint2*)(lo + (size_t)i * 4) = *(uint2*)l;
}

__global__ void wsplit(const float* __restrict__ W, __nv_bfloat16* __restrict__ Whi,
                       __nv_bfloat16* __restrict__ Wlo, int noff)
{
    __shared__ float t[32][33];
    const int n0 = blockIdx.x * 32, k0 = blockIdx.y * 32;
    const int tx = threadIdx.x & 31, ty = threadIdx.x >> 5;
#pragma unroll
    for (int i = 0; i < 32; i += 8)
        t[ty + i][tx] = W[(size_t)(k0 + ty + i) * DD + n0 + tx];
    __syncthreads();
#pragma unroll
    for (int i = 0; i < 32; i += 8) {
        __nv_bfloat16 h, l;
        spl(t[tx][ty + i], h, l);
        Whi[(size_t)(noff + n0 + ty + i) * DD + k0 + tx] = h;
        Wlo[(size_t)(noff + n0 + ty + i) * DD + k0 + tx] = l;
    }
}

#define KC 32
#define ASTRIDE 40
#define MAT_B (128*ASTRIDE*2)
#define STG_B (4*MAT_B)
#define GSM_TOTAL (2*STG_B)

__global__ __launch_bounds__(128)
void mmagemm(const __nv_bfloat16* __restrict__ Ahi, const __nv_bfloat16* __restrict__ Alo,
             const __nv_bfloat16* __restrict__ Bhi, const __nv_bfloat16* __restrict__ Blo,
             float* __restrict__ C, int cs)
{
    extern __shared__ char smem[];
    const uint32_t sb = smem_to_u32(smem);
    const int tid = threadIdx.x, l = tid & 31, wid = tid >> 5;
    const int wm = wid >> 1, wn = wid & 1;
    const int m0 = blockIdx.y * 128, n0 = blockIdx.x * 128;
    float c[4][8][4];
#pragma unroll
    for (int i = 0; i < 4; i++)
#pragma unroll
        for (int j = 0; j < 8; j++)
#pragma unroll
            for (int k = 0; k < 4; k++) c[i][j][k] = 0.f;
    const __nv_bfloat16* gsrc[4] = {Ahi + (size_t)m0 * DD, Alo + (size_t)m0 * DD,
                                    Bhi + (size_t)n0 * DD, Blo + (size_t)n0 * DD};
    const int prow = tid >> 2, pseg = tid & 3;
    {
#pragma unroll
        for (int u = 0; u < 4; u++)
#pragma unroll
            for (int mt = 0; mt < 4; mt++)
                CP_ASYNC16(sb + mt * MAT_B + (prow + u * 32) * 80 + pseg * 16,
                           gsrc[mt] + (size_t)(prow + u * 32) * DD + pseg * 8);
        CP_COMMIT();
    }
    const int arow = (l & 7) + ((l >> 3) & 1) * 8;
    const int acolh = (l >> 4) * 8;
    const int brow = (l & 7) + ((l >> 4) & 1) * 8;
    const int bcolh = ((l >> 3) & 1) * 8;
    for (int ch = 0; ch < DD / KC; ch++) {
        CP_WAIT0();
        __syncthreads();
        if (ch + 1 < DD / KC) {
            const int koff = (ch + 1) * KC;
            const uint32_t dbase = sb + ((ch + 1) & 1) * STG_B;
#pragma unroll
            for (int u = 0; u < 4; u++)
#pragma unroll
                for (int mt = 0; mt < 4; mt++)
                    CP_ASYNC16(dbase + mt * MAT_B + (prow + u * 32) * 80 + pseg * 16,
                               gsrc[mt] + (size_t)(prow + u * 32) * DD + koff + pseg * 8);
            CP_COMMIT();
        }
        const uint32_t sA = sb + (ch & 1) * STG_B;
#pragma unroll
        for (int ks = 0; ks < 2; ks++) {
            uint32_t ah[4][4], al[4][4];
#pragma unroll
            for (int mi = 0; mi < 4; mi++) {
                const uint32_t off = (uint32_t)((wm * 64 + mi * 16 + arow) * ASTRIDE + ks * 16 + acolh) * 2;
                LDSM_X4(ah[mi], sA + off);
                LDSM_X4(al[mi], sA + MAT_B + off);
            }
#pragma unroll
            for (int np = 0; np < 4; np++) {
                uint32_t bh[4], bl[4];
                const uint32_t off = (uint32_t)((wn * 64 + np * 16 + brow) * ASTRIDE + ks * 16 + bcolh) * 2;
                LDSM_X4(bh, sA + 2 * MAT_B + off);
                LDSM_X4(bl, sA + 3 * MAT_B + off);
#pragma unroll
                for (int mi = 0; mi < 4; mi++)
#pragma unroll
                    for (int nj = 0; nj < 2; nj++) {
                        MMA_B16(c[mi][np * 2 + nj], ah[mi], bh[nj * 2], bh[nj * 2 + 1]);
                        MMA_B16(c[mi][np * 2 + nj], ah[mi], bl[nj * 2], bl[nj * 2 + 1]);
                        MMA_B16(c[mi][np * 2 + nj], al[mi], bh[nj * 2], bh[nj * 2 + 1]);
                    }
            }
        }
    }
#pragma unroll
    for (int mi = 0; mi < 4; mi++)
#pragma unroll
        for (int nj = 0; nj < 8; nj++) {
            const int r0 = m0 + wm * 64 + mi * 16 + (l >> 2);
            const int cb = n0 + wn * 64 + nj * 8 + (l & 3) * 2;
            *(float2*)(C + (size_t)r0 * cs + cb)       = make_float2(c[mi][nj][0], c[mi][nj][1]);
            *(float2*)(C + (size_t)(r0 + 8) * cs + cb) = make_float2(c[mi][nj][2], c[mi][nj][3]);
        }
}

__global__ void sgemm_n4(const float* __restrict__ X, const float* __restrict__ W,
                         float* __restrict__ O)
{
    const int warp = threadIdx.x >> 5, lane = threadIdx.x & 31;
    const int row = blockIdx.x * 8 + warp;
    const float* x = X + (size_t)row * DD;
    float a0 = 0.f, a1 = 0.f, a2 = 0.f, a3 = 0.f;
    for (int k = lane; k < DD; k += 32) {
        float xv = x[k];
        float4 w = *(const float4*)(W + k * 4);
        a0 += xv * w.x; a1 += xv * w.y; a2 += xv * w.z; a3 += xv * w.w;
    }
#pragma unroll
    for (int o = 16; o; o >>= 1) {
        a0 += __shfl_xor_sync(~0u, a0, o); a1 += __shfl_xor_sync(~0u, a1, o);
        a2 += __shfl_xor_sync(~0u, a2, o); a3 += __shfl_xor_sync(~0u, a3, o);
    }
    if (lane == 0) *(float4*)(O + row * 4) = make_float4(a0, a1, a2, a3);
}

__global__ void lam_kernel(const float* __restrict__ XSG, float* __restrict__ LAM)
{
    const int b = blockIdx.x >> 2, h = blockIdx.x & 3;
    const int tid = threadIdx.x;
    __shared__ float ssum[256];
    float loc[8], run = 0.f;
    const int t0 = tid * 8;
#pragma unroll
    for (int u = 0; u < 8; u++) {
        float x = XSG[(size_t)(b * TT + t0 + u) * HH + h];
        float lg = (x >= 0.f) ? -log1pf(expf(-x)) : (x - log1pf(expf(x)));
        run += lg * (1.f / 16.f);
        loc[u] = run;
    }
    ssum[tid] = run;
    __syncthreads();
    for (int off = 1; off < 256; off <<= 1) {
        float v = (tid >= off) ? ssum[tid - off] : 0.f;
        __syncthreads();
        ssum[tid] += v;
        __syncthreads();
    }
    float excl = ssum[tid] - run;
#pragma unroll
    for (int u = 0; u < 8; u++)
        LAM[(size_t)(b * HH + h) * TT + t0 + u] = expf(excl + loc[u]);
}

#define PREP_SCAN 128
#define PREP_ROPE (PREP_SCAN + 16384)
#define PREP_VT   (PREP_ROPE + 8192)

__global__ __launch_bounds__(256)
void prep_all(const float* __restrict__ P, const float* __restrict__ LAM,
              float* __restrict__ ACC,
              __nv_bfloat16* EH, __nv_bfloat16* EL,
              __nv_bfloat16* ETH, __nv_bfloat16* ETL,
              __nv_bfloat16* QH, __nv_bfloat16* QL,
              __nv_bfloat16* KH, __nv_bfloat16* KL,
              __nv_bfloat16* VTH, __nv_bfloat16* VTL)
{
    const int bid = blockIdx.x;
    if (bid < PREP_SCAN) {
        __shared__ float sums[8][33];
        __shared__ uint16_t tph[8][32][33], tpl[8][32][33];
        const int bh = bid & 15, b = bh >> 2, h = bh & 3;
        const int ml = threadIdx.x & 31, tc = threadIdx.x >> 5;
        const int m0 = (bid >> 4) * 32;
        const int m = m0 + ml;
        const size_t src = (size_t)(b * TT) * PD + 4096 + h * 256 + m;
        const size_t dR = (size_t)bh * TT * 256 + m;
        const size_t dTb = (size_t)bh * TT * 256;
        float a = 0.f;
        for (int t = tc * 256; t < tc * 256 + 256; t++)
            a += expf(fminf(fmaxf(P[src + (size_t)t * PD], -32.f), 32.f));
        sums[tc][ml] = a;
        __syncthreads();
        a = 0.f;
        for (int p = 0; p < tc; p++) a += sums[p][ml];
        for (int seg = 0; seg < 8; seg++) {
            const int tb = tc * 256 + seg * 32;
#pragma unroll 4
            for (int u = 0; u < 32; u++) {
                const int t = tb + u;
                float e = expf(fminf(fmaxf(P[src + (size_t)t * PD], -32.f), 32.f));
                a += e;
                ACC[dR + (size_t)t * 256] = a;
                __nv_bfloat16 hh, ll;
                spl(e, hh, ll);
                EH[dR + (size_t)t * 256] = hh; EL[dR + (size_t)t * 256] = ll;
                tph[tc][u][ml] = *(uint16_t*)&hh;
                tpl[tc][u][ml] = *(uint16_t*)&ll;
            }
            __syncwarp();
#pragma unroll 4
            for (int mm = 0; mm < 32; mm++) {
                const size_t d = dTb + (size_t)(m0 + mm) * TT + tb + ml;
                uint16_t vh = tph[tc][ml][mm], vl = tpl[tc][ml][mm];
                ETH[d] = *(__nv_bfloat16*)&vh;
                ETL[d] = *(__nv_bfloat16*)&vl;
            }
            __syncwarp();
        }
    } else if (bid < PREP_ROPE) {
        const int idx = (bid - PREP_SCAN) * 256 + threadIdx.x;
        const int i = idx & 127, h = (idx >> 7) & 3, t = (idx >> 9) & 2047, b = idx >> 20;
        float inv = powf(10000.f, -(float)i * (1.f / 128.f));
        float sn, cs; sincosf((float)t * inv, &sn, &cs);
        const size_t src = (size_t)(b * TT + t) * PD + h * 256;
        const size_t dst = ((size_t)(b * HH + h) * TT + t) * 256;
        float lam = LAM[(size_t)(b * HH + h) * TT + t];
        float q1 = P[src + i], q2 = P[src + i + 128];
        float k1 = P[src + 1024 + i], k2 = P[src + 1024 + i + 128];
        float o0 = (q1 * cs - q2 * sn) * 0.0625f, o1 = (q2 * cs + q1 * sn) * 0.0625f;
        float o2 = (k1 * cs - k2 * sn) * lam,     o3 = (k2 * cs + k1 * sn) * lam;
        __nv_bfloat16 hh, ll;
        spl(o0, hh, ll); QH[dst + i] = hh;       QL[dst + i] = ll;
        spl(o1, hh, ll); QH[dst + i + 128] = hh; QL[dst + i + 128] = ll;
        spl(o2, hh, ll); KH[dst + i] = hh;       KL[dst + i] = ll;
        spl(o3, hh, ll); KH[dst + i + 128] = hh; KL[dst + i + 128] = ll;
    } else {
        __shared__ float tile[32][33];
        const int id = bid - PREP_ROPE;
        const int t0 = (id & 63) * 32, v0 = ((id >> 6) & 7) * 32, bh = id >> 9;
        const int b = bh >> 2, h = bh & 3;
        const int tx = threadIdx.x & 31, ty = threadIdx.x >> 5;
#pragma unroll
        for (int i = 0; i < 32; i += 8)
            tile[ty + i][tx] = P[(size_t)(b * TT + t0 + ty + i) * PD + 2048 + h * 256 + v0 + tx];
        __syncthreads();
#pragma unroll
        for (int i = 0; i < 32; i += 8) {
            __nv_bfloat16 hh, ll;
            spl(tile[tx][ty + i], hh, ll);
            const size_t d = (size_t)bh * TT * 256 + (size_t)(v0 + ty + i) * TT + t0 + tx;
            VTH[d] = hh; VTL[d] = ll;
        }
    }
}

// ---- warp-specialized pipelined attention (512 thr; A: warps 0-7, B: 8-15) ----
#define YB 65536
#define ZB 131072
#define SBO 196608
#define SIDX 212992
#define ASMEM 213008
#define ATHR 512
#define NTILE 512

__device__ __forceinline__ void ld_q(uint32_t sb, const __nv_bfloat16* qh,
                                     const __nv_bfloat16* ql, int tid)
{
    const int row = tid >> 3, gs = (tid & 7) * 4;
#pragma unroll
    for (int u = 0; u < 4; u++) {
        const int g = gs + u;
        const uint32_t d = sb + row * 512 + ((g ^ (row & 7)) << 4);
        CP_ASYNC16(d, qh + (size_t)row * 256 + g * 8);
        CP_ASYNC16(d + 32768, ql + (size_t)row * 256 + g * 8);
    }
}
__device__ __forceinline__ void ld_y(uint32_t sb, int st, const __nv_bfloat16* yh,
                                     const __nv_bfloat16* yl, int tid)
{
    const int row = tid >> 4, gs = (tid & 15) * 2;
#pragma unroll
    for (int u = 0; u < 2; u++) {
        const int g = gs + u;
        const uint32_t d = sb + YB + st * 32768 + row * 512 + ((g ^ (row & 7)) << 4);
        CP_ASYNC16(d, yh + (size_t)row * 256 + g * 8);
        CP_ASYNC16(d + 16384, yl + (size_t)row * 256 + g * 8);
    }
}
__device__ __forceinline__ void ld_z(uint32_t sb, int st, const __nv_bfloat16* zh,
                                     const __nv_bfloat16* zl, int tid)
{
    const int row = tid >> 1, hf = tid & 1;
    const __nv_bfloat16* s = (hf ? zl : zh) + (size_t)row * TT;
#pragma unroll
    for (int g = 0; g < 4; g++)
        CP_ASYNC16(sb + ZB + st * 32768 + row * 128 + (((g + hf * 4) ^ (row & 7)) << 4),
                   s + g * 8);
}

__device__ __forceinline__ void b_phase(uint32_t sb, int j, int wb, int l,
    int arow, int acolh, int brow, int bcolh, float ok[16][4])
{
    const int wm = wb >> 1, wnb = wb & 1;
    const uint32_t sst = sb + SBO + (j & 1) * 8192;
    const uint32_t zst = sb + ZB + (j & 1) * 32768;
#pragma unroll
    for (int ks = 0; ks < 2; ks++) {
        uint32_t ah[4], al[4];
        const int sr = wm * 16 + arow;
        const uint32_t gs = (uint32_t)(ks * 2 + (acolh >> 3));
        LDSM_X4(ah, sst + sr * 128 + ((gs ^ (sr & 7)) << 4));
        LDSM_X4(al, sst + sr * 128 + (((gs + 4) ^ (sr & 7)) << 4));
#pragma unroll
        for (int np = 0; np < 8; np++) {
            uint32_t bh4[4], bl4[4];
            const int zr = wnb * 128 + np * 16 + brow;
            const uint32_t gz = (uint32_t)(ks * 2 + (bcolh >> 3));
            LDSM_X4(bh4, zst + zr * 128 + ((gz ^ (zr & 7)) << 4));
            LDSM_X4(bl4, zst + zr * 128 + (((gz + 4) ^ (zr & 7)) << 4));
#pragma unroll
            for (int nj = 0; nj < 2; nj++) {
                MMA_B16(ok[np * 2 + nj], ah, bh4[nj * 2], bh4[nj * 2 + 1]);
                MMA_B16(ok[np * 2 + nj], ah, bl4[nj * 2], bl4[nj * 2 + 1]);
                MMA_B16(ok[np * 2 + nj], al, bh4[nj * 2], bh4[nj * 2 + 1]);
            }
        }
    }
}

__device__ __forceinline__ void stage_loop(char* sm, uint32_t sb, int qi, int tid,
    const __nv_bfloat16* Yh, const __nv_bfloat16* Yl,
    const __nv_bfloat16* Zh, const __nv_bfloat16* Zl, float ok[16][4])
{
    const int l = tid & 31, wid = tid >> 5;
    const int arow = (l & 7) + ((l >> 3) & 1) * 8, acolh = (l >> 4) * 8;
    const int brow = (l & 7) + ((l >> 4) & 1) * 8, bcolh = ((l >> 3) & 1) * 8;
    const int nk = 2 * qi + 2;
    ld_y(sb, 0, Yh, Yl, tid);
    CP_COMMIT();
    for (int kc = 0; kc < nk; kc++) {
        CP_WAIT0();
        __syncthreads();
        if (kc + 1 < nk)
            ld_y(sb, (kc + 1) & 1, Yh + (size_t)(kc + 1) * 32 * 256,
                 Yl + (size_t)(kc + 1) * 32 * 256, tid);
        ld_z(sb, kc & 1, Zh + kc * 32, Zl + kc * 32, tid);
        CP_COMMIT();
        if (wid < 8) {
            const int wm = wid >> 1, wn = wid & 1;
            float s4[2][4];
#pragma unroll
            for (int j = 0; j < 2; j++)
#pragma unroll
                for (int k = 0; k < 4; k++) s4[j][k] = 0.f;
            const uint32_t yst = sb + YB + (kc & 1) * 32768;
#pragma unroll 4
            for (int ks = 0; ks < 16; ks++) {
                uint32_t ah[4], al[4], bh4[4], bl4[4];
                const int xr = wm * 16 + arow;
                const uint32_t gq = (uint32_t)(ks * 2 + (acolh >> 3));
                const uint32_t ax = sb + xr * 512 + ((gq ^ (xr & 7)) << 4);
                LDSM_X4(ah, ax);
                LDSM_X4(al, ax + 32768);
                const int yr = wn * 16 + brow;
                const uint32_t gy = (uint32_t)(ks * 2 + (bcolh >> 3));
                const uint32_t ay = yst + yr * 512 + ((gy ^ (yr & 7)) << 4);
                LDSM_X4(bh4, ay);
                LDSM_X4(bl4, ay + 16384);
#pragma unroll
                for (int nj = 0; nj < 2; nj++) {
                    MMA_B16(s4[nj], ah, bh4[nj * 2], bh4[nj * 2 + 1]);
                    MMA_B16(s4[nj], ah, bl4[nj * 2], bl4[nj * 2 + 1]);
                    MMA_B16(s4[nj], al, bh4[nj * 2], bh4[nj * 2 + 1]);
                }
            }
            const uint32_t soff = SBO + (uint32_t)(kc & 1) * 8192;
#pragma unroll
            for (int nj = 0; nj < 2; nj++)
#pragma unroll
                for (int hf = 0; hf < 2; hf++) {
                    const int r = wm * 16 + (l >> 2) + hf * 8;
                    const int c = wn * 16 + nj * 8 + (l & 3) * 2;
                    float v0 = s4[nj][hf * 2], v1 = s4[nj][hf * 2 + 1];
                    if (kc >= nk - 2) {
                        const int tg = (kc - (nk - 2)) * 32 + c;
                        if (tg > r) v0 = 0.f;
                        if (tg + 1 > r) v1 = 0.f;
                    }
                    __nv_bfloat16 h0, l0, h1, l1;
                    spl(v0, h0, l0); spl(v1, h1, l1);
                    const uint32_t gS = (uint32_t)(c >> 3);
                    const uint32_t rb = soff + r * 128 + (c & 7) * 2;
                    *(uint32_t*)(sm + rb + ((gS ^ (r & 7)) << 4)) = pkbf(h0, h1);
                    *(uint32_t*)(sm + rb + (((gS + 4) ^ (r & 7)) << 4)) = pkbf(l0, l1);
                }
        } else if (kc > 0) {
            b_phase(sb, kc - 1, wid - 8, l, arow, acolh, brow, bcolh, ok);
        }
    }
    CP_WAIT0();
    __syncthreads();
    if (wid >= 8) b_phase(sb, nk - 1, wid - 8, l, arow, acolh, brow, bcolh, ok);
    __syncthreads();
}

__device__ __forceinline__ void dump_ok(char* sm, float ok[16][4], int wb, int l)
{
    float* OKS = (float*)(sm + YB);
    const int wm = wb >> 1, wnb = wb & 1;
#pragma unroll
    for (int idx = 0; idx < 16; idx++)
#pragma unroll
        for (int hf = 0; hf < 2; hf++) {
            const int r = wm * 16 + (l >> 2) + hf * 8;
            const int c = wnb * 128 + idx * 8 + (l & 3) * 2;
            *(float2*)&OKS[r * 258 + c] = make_float2(ok[idx][hf * 2], ok[idx][hf * 2 + 1]);
            ok[idx][hf * 2] = 0.f; ok[idx][hf * 2 + 1] = 0.f;
        }
}

__global__ __launch_bounds__(ATHR)
void attn_fused(const __nv_bfloat16* __restrict__ QH, const __nv_bfloat16* __restrict__ QL,
                const __nv_bfloat16* __restrict__ KH, const __nv_bfloat16* __restrict__ KL,
                const __nv_bfloat16* __restrict__ ETH, const __nv_bfloat16* __restrict__ ETL,
                const __nv_bfloat16* __restrict__ EH, const __nv_bfloat16* __restrict__ EL,
                const __nv_bfloat16* __restrict__ VTH, const __nv_bfloat16* __restrict__ VTL,
                const float* __restrict__ ACC, const float* __restrict__ P,
                const float* __restrict__ gnw, int* __restrict__ ctr,
                __nv_bfloat16* __restrict__ AH, __nv_bfloat16* __restrict__ AL)
{
    extern __shared__ char sm[];
    const uint32_t sb = smem_to_u32(sm);
    const int tid = threadIdx.x, l = tid & 31, wid = tid >> 5;

    float ok[16][4];
#pragma unroll
    for (int j = 0; j < 16; j++)
#pragma unroll
        for (int k = 0; k < 4; k++) ok[j][k] = 0.f;

    float* OKS = (float*)(sm + YB);

    for (;;) {
        if (tid == 0) *(int*)(sm + SIDX) = atomicAdd(ctr, 1);
        __syncthreads();
        const int widx = *(int*)(sm + SIDX);
        __syncthreads();
        if (widx >= NTILE) break;

        const int qi = 31 - (widx >> 4);
        const int bh = widx & 15;
        const int b = bh >> 2, h = bh & 3;
        const int qBase = qi * 64;
        const size_t base = (size_t)bh * TT * 256;

        ld_q(sb, QH + base + (size_t)qBase * 256, QL + base + (size_t)qBase * 256, tid);
        stage_loop(sm, sb, qi, tid, KH + base, KL + base, ETH + base, ETL + base, ok);

        if (wid >= 8) dump_ok(sm, ok, wid - 8, l);
        __syncthreads();
#pragma unroll
        for (int i = 0; i < 4; i++) {
            const int r = wid * 4 + i, t = qBase + r;
            float v[8], acr[8], mx = -3.4e38f;
#pragma unroll
            for (int j = 0; j < 8; j++) {
                const int c = j * 32 + l;
                acr[j] = ACC[base + (size_t)t * 256 + c];
                v[j] = OKS[r * 258 + c] / acr[j];
                mx = fmaxf(mx, v[j]);
            }
#pragma unroll
            for (int o = 16; o; o >>= 1) mx = fmaxf(mx, __shfl_xor_sync(~0u, mx, o));
            float e[8], s = 0.f;
#pragma unroll
            for (int j = 0; j < 8; j++) { e[j] = expf(v[j] - mx); s += e[j]; }
#pragma unroll
            for (int o = 16; o; o >>= 1) s += __shfl_xor_sync(~0u, s, o);
            const float inv = 1.f / s;
#pragma unroll
            for (int j = 0; j < 8; j++) {
                const int c = j * 32 + l;
                __nv_bfloat16 hh, ll;
                spl(e[j] * inv / acr[j], hh, ll);
                const uint32_t uo = (uint32_t)(r * 512 + ((((uint32_t)(c >> 3)) ^ (r & 7)) << 4) + (c & 7) * 2);
                *(__nv_bfloat16*)(sm + uo) = hh;
                *(__nv_bfloat16*)(sm + 32768 + uo) = ll;
            }
        }
        __syncthreads();

        stage_loop(sm, sb, qi, tid, EH + base, EL + base, VTH + base, VTL + base, ok);

        if (wid >= 8) dump_ok(sm, ok, wid - 8, l);
        __syncthreads();
#pragma unroll
        for (int i = 0; i < 4; i++) {
            const int r = wid * 4 + i, t = qBase + r;
            float vv[8], ss = 0.f;
#pragma unroll
            for (int j = 0; j < 8; j++) { vv[j] = OKS[r * 258 + j * 32 + l]; ss += vv[j] * vv[j]; }
#pragma unroll
            for (int o = 16; o; o >>= 1) ss += __shfl_xor_sync(~0u, ss, o);
            const float rn = rsqrtf(ss * (1.f / 256.f) + 1e-5f);
#pragma unroll
            for (int j = 0; j < 8; j++) {
                const int c = j * 32 + l;
                float gg = P[(size_t)(b * TT + t) * PD + 3072 + h * 256 + c];
                float sig = 1.f / (1.f + expf(-gg));
                float act = vv[j] * rn * gnw[c] * gg * sig;
                __nv_bfloat16 hh, ll;
                spl(act, hh, ll);
                AH[(size_t)(b * TT + t) * DD + h * 256 + c] = hh;
                AL[(size_t)(b * TT + t) * DD + h * 256 + c] = ll;
            }
        }
        __syncthreads();
    }
}

extern "C" void kernel_launch(void* const* d_in, const int* in_sizes, int n_in,
                              void* d_out, int out_size)
{
    const float* x   = (const float*)d_in[0];
    const float* qw  = (const float*)d_in[1];
    const float* kw  = (const float*)d_in[2];
    const float* vw  = (const float*)d_in[3];
    const float* gw  = (const float*)d_in[4];
    const float* sw  = (const float*)d_in[5];
    const float* sgw = (const float*)d_in[6];
    const float* gnw = (const float*)d_in[7];
    const float* ow  = (const float*)d_in[8];
    float* out = (float*)d_out;

    float *P, *ACC, *XSG, *LAM;
    int* CTR;
    __nv_bfloat16 *XHI, *XLO, *WHI, *WLO, *QHI, *QLO, *KHI, *KLO;
    __nv_bfloat16 *EHI, *ELO, *ETHI, *ETLO, *VTHI, *VTLO;
    cudaGetSymbolAddress((void**)&P, g_P);     cudaGetSymbolAddress((void**)&ACC, g_ACC);
    cudaGetSymbolAddress((void**)&XSG, g_XSG); cudaGetSymbolAddress((void**)&LAM, g_LAM);
    cudaGetSymbolAddress((void**)&CTR, g_ctr);
    cudaGetSymbolAddress((void**)&XHI, g_XHI); cudaGetSymbolAddress((void**)&XLO, g_XLO);
    cudaGetSymbolAddress((void**)&WHI, g_WHI); cudaGetSymbolAddress((void**)&WLO, g_WLO);
    cudaGetSymbolAddress((void**)&QHI, g_QHI); cudaGetSymbolAddress((void**)&QLO, g_QLO);
    cudaGetSymbolAddress((void**)&KHI, g_KHI); cudaGetSymbolAddress((void**)&KLO, g_KLO);
    cudaGetSymbolAddress((void**)&EHI, g_EHI); cudaGetSymbolAddress((void**)&ELO, g_ELO);
    cudaGetSymbolAddress((void**)&ETHI, g_ETHI); cudaGetSymbolAddress((void**)&ETLO, g_ETLO);
    cudaGetSymbolAddress((void**)&VTHI, g_VTHI); cudaGetSymbolAddress((void**)&VTLO, g_VTLO);

    static int done = 0;
    if (!done) {
        cudaFuncSetAttribute(mmagemm, cudaFuncAttributeMaxDynamicSharedMemorySize, GSM_TOTAL);
        cudaFuncSetAttribute(attn_fused, cudaFuncAttributeMaxDynamicSharedMemorySize, ASMEM);
        done = 1;
    }

    const dim3 wgrid(32, 32);
    const int sxg = (BT * DD / 4) / 256;

    cudaMemsetAsync(CTR, 0, sizeof(int));
    splitx<<<sxg, 256>>>(x, XHI, XLO);
    sgemm_n4<<<BT / 8, 256>>>(x, sgw, XSG);
    lam_kernel<<<BH, 256>>>(XSG, LAM);
    wsplit<<<wgrid, 256>>>(qw, WHI, WLO, 0);
    wsplit<<<wgrid, 256>>>(kw, WHI, WLO, 1024);
    wsplit<<<wgrid, 256>>>(vw, WHI, WLO, 2048);
    wsplit<<<wgrid, 256>>>(gw, WHI, WLO, 3072);
    wsplit<<<wgrid, 256>>>(sw, WHI, WLO, 4096);
    mmagemm<<<dim3(PD / 128, BT / 128), 128, GSM_TOTAL>>>(XHI, XLO, WHI, WLO, P, PD);

    prep_all<<<PREP_VT, 256>>>(P, LAM, ACC, EHI, ELO, ETHI, ETLO,
                               QHI, QLO, KHI, KLO, VTHI, VTLO);

    attn_fused<<<148, ATHR, ASMEM>>>(QHI, QLO, KHI, KLO, ETHI, ETLO,
                                     EHI, ELO, VTHI, VTLO, ACC, P, gnw, CTR,
                                     XHI, XLO);

    wsplit<<<wgrid, 256>>>(ow, WHI, WLO, 0);
    mmagemm<<<dim3(DD / 128, BT / 128), 128, GSM_TOTAL>>>(XHI, XLO, WHI, WLO, out, DD);
}

// round 15
// speedup vs baseline: 1.0473x; 1.0473x over previous
#include <cuda_runtime.h>
#include <cuda_bf16.h>
#include <math.h>
#include <stdint.h>

#define BB 4
#define TT 2048
#define HH 4
#define DD 1024
#define PD 5120
#define BT (BB*TT)
#define BH 16

__device__ float g_P[(size_t)BT*PD], g_ACC[BT*DD], g_XSG[BT*HH], g_LAM[BH*TT];
__device__ int g_ctr;
__device__ __nv_bfloat16 g_XHI[BT*DD], g_XLO[BT*DD], g_WHI[(size_t)PD*DD], g_WLO[(size_t)PD*DD];
__device__ __nv_bfloat16 g_WOHI[DD*DD], g_WOLO[DD*DD];
__device__ __nv_bfloat16 g_QHI[BT*DD], g_QLO[BT*DD], g_KHI[BT*DD], g_KLO[BT*DD];
__device__ __nv_bfloat16 g_EHI[BT*DD], g_ELO[BT*DD], g_ETHI[BT*DD], g_ETLO[BT*DD];
__device__ __nv_bfloat16 g_VTHI[BT*DD], g_VTLO[BT*DD];

__device__ __forceinline__ uint32_t smem_to_u32(const void* p) {
    uint32_t a;
    asm("{ .reg .u64 t; cvta.to.shared.u64 t, %1; cvt.u32.u64 %0, t; }" : "=r"(a) : "l"(p));
    return a;
}
#define CP_ASYNC16(d, s) asm volatile("cp.async.cg.shared.global [%0], [%1], 16;" :: "r"(d), "l"(s))
#define CP_COMMIT() asm volatile("cp.async.commit_group;" ::: "memory")
#define CP_WAIT0() asm volatile("cp.async.wait_group 0;" ::: "memory")
#define LDSM_X4(r, a) \
    asm volatile("ldmatrix.sync.aligned.m8n8.x4.shared.b16 {%0,%1,%2,%3}, [%4];" \
        : "=r"((r)[0]),"=r"((r)[1]),"=r"((r)[2]),"=r"((r)[3]) : "r"(a))
#define MMA_B16(c, a, b0, b1) \
    asm volatile("mma.sync.aligned.m16n8k16.row.col.f32.bf16.bf16.f32 " \
        "{%0,%1,%2,%3},{%4,%5,%6,%7},{%8,%9},{%0,%1,%2,%3};" \
        : "+f"((c)[0]),"+f"((c)[1]),"+f"((c)[2]),"+f"((c)[3]) \
        : "r"((a)[0]),"r"((a)[1]),"r"((a)[2]),"r"((a)[3]), "r"(b0),"r"(b1))
__device__ __forceinline__ void spl(float x, __nv_bfloat16& h, __nv_bfloat16& l) {
    h = __float2bfloat16(x); l = __float2bfloat16(x - __bfloat162float(h));
}
__device__ __forceinline__ uint32_t pkbf(__nv_bfloat16 a, __nv_bfloat16 b) {
    return (uint32_t)*(uint16_t*)&a | ((uint32_t)*(uint16_t*)&b << 16);
}

// blocks [0,8192): X bf16 split; [8192,9216): XSG = X @ sgw; resets ctr
__global__ void splitx_plus(const float* __restrict__ X, __nv_bfloat16* __restrict__ hi,
                            __nv_bfloat16* __restrict__ lo, const float* __restrict__ W,
                            float* __restrict__ O, int* __restrict__ ctr)
{
    const int bid = blockIdx.x;
    if (bid < 8192) {
        const int i = bid * 256 + threadIdx.x;
        float4 v = *(const float4*)(X + (size_t)i * 4);
        __nv_bfloat16 h[4], l[4];
        float vv[4] = {v.x, v.y, v.z, v.w};
#pragma unroll
        for (int j = 0; j < 4; j++) spl(vv[j], h[j], l[j]);
        *(uint2*)(hi + (size_t)i * 4) = *(uint2*)h;
        *(uint2*)(lo + (size_t)i * 4) = *(uint2*)l;
    } else {
        if (bid == 8192 && threadIdx.x == 0) *ctr = 0;
        const int warp = threadIdx.x >> 5, lane = threadIdx.x & 31;
        const int row = (bid - 8192) * 8 + warp;
        const float* x = X + (size_t)row * DD;
        float a0 = 0.f, a1 = 0.f, a2 = 0.f, a3 = 0.f;
        for (int k = lane; k < DD; k += 32) {
            float xv = x[k];
            float4 w = *(const float4*)(W + k * 4);
            a0 += xv * w.x; a1 += xv * w.y; a2 += xv * w.z; a3 += xv * w.w;
        }
#pragma unroll
        for (int o = 16; o; o >>= 1) {
            a0 += __shfl_xor_sync(~0u, a0, o); a1 += __shfl_xor_sync(~0u, a1, o);
            a2 += __shfl_xor_sync(~0u, a2, o); a3 += __shfl_xor_sync(~0u, a3, o);
        }
        if (lane == 0) *(float4*)(O + row * 4) = make_float4(a0, a1, a2, a3);
    }
}

// z = 0..4: qw/kw/vw/gw/sw -> WHI/WLO at noff=z*1024 ; z=5: ow -> WOHI/WOLO
__global__ void wsplit_all(const float* __restrict__ w0, const float* __restrict__ w1,
                           const float* __restrict__ w2, const float* __restrict__ w3,
                           const float* __restrict__ w4, const float* __restrict__ w5,
                           __nv_bfloat16* __restrict__ WHI, __nv_bfloat16* __restrict__ WLO,
                           __nv_bfloat16* __restrict__ WOHI, __nv_bfloat16* __restrict__ WOLO)
{
    __shared__ float t[32][33];
    const int z = blockIdx.z;
    const float* W = (z == 0) ? w0 : (z == 1) ? w1 : (z == 2) ? w2 :
                     (z == 3) ? w3 : (z == 4) ? w4 : w5;
    __nv_bfloat16* Whi = (z < 5) ? WHI : WOHI;
    __nv_bfloat16* Wlo = (z < 5) ? WLO : WOLO;
    const int noff = (z < 5) ? z * 1024 : 0;
    const int n0 = blockIdx.x * 32, k0 = blockIdx.y * 32;
    const int tx = threadIdx.x & 31, ty = threadIdx.x >> 5;
#pragma unroll
    for (int i = 0; i < 32; i += 8)
        t[ty + i][tx] = W[(size_t)(k0 + ty + i) * DD + n0 + tx];
    __syncthreads();
#pragma unroll
    for (int i = 0; i < 32; i += 8) {
        __nv_bfloat16 h, l;
        spl(t[tx][ty + i], h, l);
        Whi[(size_t)(noff + n0 + ty + i) * DD + k0 + tx] = h;
        Wlo[(size_t)(noff + n0 + ty + i) * DD + k0 + tx] = l;
    }
}

#define KC 32
#define ASTRIDE 40
#define MAT_B (128*ASTRIDE*2)
#define STG_B (4*MAT_B)
#define GSM_TOTAL (2*STG_B)

__global__ __launch_bounds__(128)
void mmagemm(const __nv_bfloat16* __restrict__ Ahi, const __nv_bfloat16* __restrict__ Alo,
             const __nv_bfloat16* __restrict__ Bhi, const __nv_bfloat16* __restrict__ Blo,
             float* __restrict__ C, int cs)
{
    extern __shared__ char smem[];
    const uint32_t sb = smem_to_u32(smem);
    const int tid = threadIdx.x, l = tid & 31, wid = tid >> 5;
    const int wm = wid >> 1, wn = wid & 1;
    const int m0 = blockIdx.y * 128, n0 = blockIdx.x * 128;
    float c[4][8][4];
#pragma unroll
    for (int i = 0; i < 4; i++)
#pragma unroll
        for (int j = 0; j < 8; j++)
#pragma unroll
            for (int k = 0; k < 4; k++) c[i][j][k] = 0.f;
    const __nv_bfloat16* gsrc[4] = {Ahi + (size_t)m0 * DD, Alo + (size_t)m0 * DD,
                                    Bhi + (size_t)n0 * DD, Blo + (size_t)n0 * DD};
    const int prow = tid >> 2, pseg = tid & 3;
    {
#pragma unroll
        for (int u = 0; u < 4; u++)
#pragma unroll
            for (int mt = 0; mt < 4; mt++)
                CP_ASYNC16(sb + mt * MAT_B + (prow + u * 32) * 80 + pseg * 16,
                           gsrc[mt] + (size_t)(prow + u * 32) * DD + pseg * 8);
        CP_COMMIT();
    }
    const int arow = (l & 7) + ((l >> 3) & 1) * 8;
    const int acolh = (l >> 4) * 8;
    const int brow = (l & 7) + ((l >> 4) & 1) * 8;
    const int bcolh = ((l >> 3) & 1) * 8;
    for (int ch = 0; ch < DD / KC; ch++) {
        CP_WAIT0();
        __syncthreads();
        if (ch + 1 < DD / KC) {
            const int koff = (ch + 1) * KC;
            const uint32_t dbase = sb + ((ch + 1) & 1) * STG_B;
#pragma unroll
            for (int u = 0; u < 4; u++)
#pragma unroll
                for (int mt = 0; mt < 4; mt++)
                    CP_ASYNC16(dbase + mt * MAT_B + (prow + u * 32) * 80 + pseg * 16,
                               gsrc[mt] + (size_t)(prow + u * 32) * DD + koff + pseg * 8);
            CP_COMMIT();
        }
        const uint32_t sA = sb + (ch & 1) * STG_B;
#pragma unroll
        for (int ks = 0; ks < 2; ks++) {
            uint32_t ah[4][4], al[4][4];
#pragma unroll
            for (int mi = 0; mi < 4; mi++) {
                const uint32_t off = (uint32_t)((wm * 64 + mi * 16 + arow) * ASTRIDE + ks * 16 + acolh) * 2;
                LDSM_X4(ah[mi], sA + off);
                LDSM_X4(al[mi], sA + MAT_B + off);
            }
#pragma unroll
            for (int np = 0; np < 4; np++) {
                uint32_t bh[4], bl[4];
                const uint32_t off = (uint32_t)((wn * 64 + np * 16 + brow) * ASTRIDE + ks * 16 + bcolh) * 2;
                LDSM_X4(bh, sA + 2 * MAT_B + off);
                LDSM_X4(bl, sA + 3 * MAT_B + off);
#pragma unroll
                for (int mi = 0; mi < 4; mi++)
#pragma unroll
                    for (int nj = 0; nj < 2; nj++) {
                        MMA_B16(c[mi][np * 2 + nj], ah[mi], bh[nj * 2], bh[nj * 2 + 1]);
                        MMA_B16(c[mi][np * 2 + nj], ah[mi], bl[nj * 2], bl[nj * 2 + 1]);
                        MMA_B16(c[mi][np * 2 + nj], al[mi], bh[nj * 2], bh[nj * 2 + 1]);
                    }
            }
        }
    }
#pragma unroll
    for (int mi = 0; mi < 4; mi++)
#pragma unroll
        for (int nj = 0; nj < 8; nj++) {
            const int r0 = m0 + wm * 64 + mi * 16 + (l >> 2);
            const int cb = n0 + wn * 64 + nj * 8 + (l & 3) * 2;
            *(float2*)(C + (size_t)r0 * cs + cb)       = make_float2(c[mi][nj][0], c[mi][nj][1]);
            *(float2*)(C + (size_t)(r0 + 8) * cs + cb) = make_float2(c[mi][nj][2], c[mi][nj][3]);
        }
}

__global__ void lam_kernel(const float* __restrict__ XSG, float* __restrict__ LAM)
{
    const int b = blockIdx.x >> 2, h = blockIdx.x & 3;
    const int tid = threadIdx.x;
    __shared__ float ssum[256];
    float loc[8], run = 0.f;
    const int t0 = tid * 8;
#pragma unroll
    for (int u = 0; u < 8; u++) {
        float x = XSG[(size_t)(b * TT + t0 + u) * HH + h];
        float lg = (x >= 0.f) ? -log1pf(expf(-x)) : (x - log1pf(expf(x)));
        run += lg * (1.f / 16.f);
        loc[u] = run;
    }
    ssum[tid] = run;
    __syncthreads();
    for (int off = 1; off < 256; off <<= 1) {
        float v = (tid >= off) ? ssum[tid - off] : 0.f;
        __syncthreads();
        ssum[tid] += v;
        __syncthreads();
    }
    float excl = ssum[tid] - run;
#pragma unroll
    for (int u = 0; u < 8; u++)
        LAM[(size_t)(b * HH + h) * TT + t0 + u] = expf(excl + loc[u]);
}

#define PREP_SCAN 128
#define PREP_ROPE (PREP_SCAN + 16384)
#define PREP_VT   (PREP_ROPE + 8192)

__global__ __launch_bounds__(256)
void prep_all(const float* __restrict__ P, const float* __restrict__ LAM,
              float* __restrict__ ACC,
              __nv_bfloat16* EH, __nv_bfloat16* EL,
              __nv_bfloat16* ETH, __nv_bfloat16* ETL,
              __nv_bfloat16* QH, __nv_bfloat16* QL,
              __nv_bfloat16* KH, __nv_bfloat16* KL,
              __nv_bfloat16* VTH, __nv_bfloat16* VTL)
{
    const int bid = blockIdx.x;
    if (bid < PREP_SCAN) {
        __shared__ float sums[8][33];
        __shared__ uint16_t tph[8][32][33], tpl[8][32][33];
        const int bh = bid & 15, b = bh >> 2, h = bh & 3;
        const int ml = threadIdx.x & 31, tc = threadIdx.x >> 5;
        const int m0 = (bid >> 4) * 32;
        const int m = m0 + ml;
        const size_t src = (size_t)(b * TT) * PD + 4096 + h * 256 + m;
        const size_t dR = (size_t)bh * TT * 256 + m;
        const size_t dTb = (size_t)bh * TT * 256;
        float a = 0.f;
        for (int t = tc * 256; t < tc * 256 + 256; t++)
            a += expf(fminf(fmaxf(P[src + (size_t)t * PD], -32.f), 32.f));
        sums[tc][ml] = a;
        __syncthreads();
        a = 0.f;
        for (int p = 0; p < tc; p++) a += sums[p][ml];
        for (int seg = 0; seg < 8; seg++) {
            const int tb = tc * 256 + seg * 32;
#pragma unroll 4
            for (int u = 0; u < 32; u++) {
                const int t = tb + u;
                float e = expf(fminf(fmaxf(P[src + (size_t)t * PD], -32.f), 32.f));
                a += e;
                ACC[dR + (size_t)t * 256] = a;
                __nv_bfloat16 hh, ll;
                spl(e, hh, ll);
                EH[dR + (size_t)t * 256] = hh; EL[dR + (size_t)t * 256] = ll;
                tph[tc][u][ml] = *(uint16_t*)&hh;
                tpl[tc][u][ml] = *(uint16_t*)&ll;
            }
            __syncwarp();
#pragma unroll 4
            for (int mm = 0; mm < 32; mm++) {
                const size_t d = dTb + (size_t)(m0 + mm) * TT + tb + ml;
                uint16_t vh = tph[tc][ml][mm], vl = tpl[tc][ml][mm];
                ETH[d] = *(__nv_bfloat16*)&vh;
                ETL[d] = *(__nv_bfloat16*)&vl;
            }
            __syncwarp();
        }
    } else if (bid < PREP_ROPE) {
        const int idx = (bid - PREP_SCAN) * 256 + threadIdx.x;
        const int i = idx & 127, h = (idx >> 7) & 3, t = (idx >> 9) & 2047, b = idx >> 20;
        float inv = powf(10000.f, -(float)i * (1.f / 128.f));
        float sn, cs; sincosf((float)t * inv, &sn, &cs);
        const size_t src = (size_t)(b * TT + t) * PD + h * 256;
        const size_t dst = ((size_t)(b * HH + h) * TT + t) * 256;
        float lam = LAM[(size_t)(b * HH + h) * TT + t];
        float q1 = P[src + i], q2 = P[src + i + 128];
        float k1 = P[src + 1024 + i], k2 = P[src + 1024 + i + 128];
        float o0 = (q1 * cs - q2 * sn) * 0.0625f, o1 = (q2 * cs + q1 * sn) * 0.0625f;
        float o2 = (k1 * cs - k2 * sn) * lam,     o3 = (k2 * cs + k1 * sn) * lam;
        __nv_bfloat16 hh, ll;
        spl(o0, hh, ll); QH[dst + i] = hh;       QL[dst + i] = ll;
        spl(o1, hh, ll); QH[dst + i + 128] = hh; QL[dst + i + 128] = ll;
        spl(o2, hh, ll); KH[dst + i] = hh;       KL[dst + i] = ll;
        spl(o3, hh, ll); KH[dst + i + 128] = hh; KL[dst + i + 128] = ll;
    } else {
        __shared__ float tile[32][33];
        const int id = bid - PREP_ROPE;
        const int t0 = (id & 63) * 32, v0 = ((id >> 6) & 7) * 32, bh = id >> 9;
        const int b = bh >> 2, h = bh & 3;
        const int tx = threadIdx.x & 31, ty = threadIdx.x >> 5;
#pragma unroll
        for (int i = 0; i < 32; i += 8)
            tile[ty + i][tx] = P[(size_t)(b * TT + t0 + ty + i) * PD + 2048 + h * 256 + v0 + tx];
        __syncthreads();
#pragma unroll
        for (int i = 0; i < 32; i += 8) {
            __nv_bfloat16 hh, ll;
            spl(tile[tx][ty + i], hh, ll);
            const size_t d = (size_t)bh * TT * 256 + (size_t)(v0 + ty + i) * TT + t0 + tx;
            VTH[d] = hh; VTL[d] = ll;
        }
    }
}

// ---- fused attention: persistent work-stealing, 512 threads (R11 version) ----
#define QSH 0
#define QSL 33792
#define YSH 67584
#define YSL 101376
#define ZSH 135168
#define ZSL 172032
#define SSH 208896
#define SSL 218112
#define SIDX 227328
#define ASMEM 227344
#define XSTR 264
#define ZSTR 72
#define ATHR 512
#define NTILE 512

__device__ __forceinline__ void ld_xy(uint32_t dH, uint32_t dL,
    const __nv_bfloat16* sH, const __nv_bfloat16* sL, int tid)
{
    const int pr = tid >> 3, ps = tid & 7;
    const __nv_bfloat16* h = sH + (size_t)pr * 256;
    const __nv_bfloat16* l = sL + (size_t)pr * 256;
#pragma unroll
    for (int s = ps; s < 32; s += 8) {
        CP_ASYNC16(dH + pr * XSTR * 2 + s * 16, h + s * 8);
        CP_ASYNC16(dL + pr * XSTR * 2 + s * 16, l + s * 8);
    }
}
__device__ __forceinline__ void ld_z(uint32_t sb,
    const __nv_bfloat16* zH, const __nv_bfloat16* zL, int tid)
{
    const int row = tid >> 1, hf = tid & 1;
    const __nv_bfloat16* h = zH + (size_t)row * TT;
    const __nv_bfloat16* l = zL + (size_t)row * TT;
#pragma unroll
    for (int s = hf * 4; s < hf * 4 + 4; s++) {
        CP_ASYNC16(sb + ZSH + row * ZSTR * 2 + s * 16, h + s * 8);
        CP_ASYNC16(sb + ZSL + row * ZSTR * 2 + s * 16, l + s * 8);
    }
}

__device__ __forceinline__ void stage_loop(char* sm, uint32_t sb, int qi, int tid,
    const __nv_bfloat16* YHb, const __nv_bfloat16* YLb,
    const __nv_bfloat16* ZHb, const __nv_bfloat16* ZLb, float ok[8][4])
{
    const int l = tid & 31, wid = tid >> 5, wm = wid >> 2, wn = wid & 3;
    const int arow = (l & 7) + ((l >> 3) & 1) * 8, acolh = (l >> 4) * 8;
    const int brow = (l & 7) + ((l >> 4) & 1) * 8, bcolh = ((l >> 3) & 1) * 8;
    ld_xy(sb + YSH, sb + YSL, YHb, YLb, tid); CP_COMMIT();
    ld_z(sb, ZHb, ZLb, tid); CP_COMMIT();
    for (int kc = 0; kc <= qi; kc++) {
        asm volatile("cp.async.wait_group 1;" ::: "memory");
        __syncthreads();
        float s4[2][4];
#pragma unroll
        for (int j = 0; j < 2; j++)
#pragma unroll
            for (int k = 0; k < 4; k++) s4[j][k] = 0.f;
#pragma unroll 4
        for (int ks = 0; ks < 16; ks++) {
            uint32_t ah[4], al[4], bhf[4], blf[4];
            const uint32_t ao = (uint32_t)((wm * 16 + arow) * XSTR + ks * 16 + acolh) * 2;
            LDSM_X4(ah, sb + QSH + ao);
            LDSM_X4(al, sb + QSL + ao);
            const uint32_t bo = (uint32_t)((wn * 16 + brow) * XSTR + ks * 16 + bcolh) * 2;
            LDSM_X4(bhf, sb + YSH + bo);
            LDSM_X4(blf, sb + YSL + bo);
#pragma unroll
            for (int nj = 0; nj < 2; nj++) {
                MMA_B16(s4[nj], ah, bhf[nj * 2], bhf[nj * 2 + 1]);
                MMA_B16(s4[nj], ah, blf[nj * 2], blf[nj * 2 + 1]);
                MMA_B16(s4[nj], al, bhf[nj * 2], bhf[nj * 2 + 1]);
            }
        }
        __syncthreads();
        const bool diag = (kc == qi);
#pragma unroll
        for (int nj = 0; nj < 2; nj++)
#pragma unroll
            for (int hf = 0; hf < 2; hf++) {
                const int r = wm * 16 + (l >> 2) + hf * 8;
                const int c = wn * 16 + nj * 8 + (l & 3) * 2;
                float v0 = s4[nj][hf * 2], v1 = s4[nj][hf * 2 + 1];
                if (diag) { if (c > r) v0 = 0.f; if (c + 1 > r) v1 = 0.f; }
                __nv_bfloat16 h0, l0, h1, l1;
                spl(v0, h0, l0); spl(v1, h1, l1);
                *(uint32_t*)(sm + SSH + (r * ZSTR + c) * 2) = pkbf(h0, h1);
                *(uint32_t*)(sm + SSL + (r * ZSTR + c) * 2) = pkbf(l0, l1);
            }
        if (kc < qi) {
            ld_xy(sb + YSH, sb + YSL, YHb + (size_t)(kc + 1) * 64 * 256,
                  YLb + (size_t)(kc + 1) * 64 * 256, tid);
            CP_COMMIT();
        }
        if (kc == qi) asm volatile("cp.async.wait_group 0;" ::: "memory");
        else          asm volatile("cp.async.wait_group 1;" ::: "memory");
        __syncthreads();
#pragma unroll
        for (int ks = 0; ks < 4; ks++) {
            uint32_t ah[4], al[4];
            const uint32_t ao = (uint32_t)((wm * 16 + arow) * ZSTR + ks * 16 + acolh) * 2;
            LDSM_X4(ah, sb + SSH + ao);
            LDSM_X4(al, sb + SSL + ao);
#pragma unroll
            for (int np = 0; np < 4; np++) {
                uint32_t bhf[4], blf[4];
                const uint32_t bo = (uint32_t)((wn * 64 + np * 16 + brow) * ZSTR + ks * 16 + bcolh) * 2;
                LDSM_X4(bhf, sb + ZSH + bo);
                LDSM_X4(blf, sb + ZSL + bo);
#pragma unroll
                for (int nj = 0; nj < 2; nj++) {
                    MMA_B16(ok[np * 2 + nj], ah, bhf[nj * 2], bhf[nj * 2 + 1]);
                    MMA_B16(ok[np * 2 + nj], ah, blf[nj * 2], blf[nj * 2 + 1]);
                    MMA_B16(ok[np * 2 + nj], al, bhf[nj * 2], bhf[nj * 2 + 1]);
                }
            }
        }
        __syncthreads();
        if (kc < qi) { ld_z(sb, ZHb + (kc + 1) * 64, ZLb + (kc + 1) * 64, tid); CP_COMMIT(); }
    }
}

__device__ __forceinline__ void dump_ok(char* sm, float ok[8][4], int wm, int wn, int l)
{
    float* OKS = (float*)(sm + YSH);
#pragma unroll
    for (int idx = 0; idx < 8; idx++)
#pragma unroll
        for (int hf = 0; hf < 2; hf++) {
            const int r = wm * 16 + (l >> 2) + hf * 8;
            const int c = wn * 64 + idx * 8 + (l & 3) * 2;
            *(float2*)&OKS[r * 258 + c] = make_float2(ok[idx][hf * 2], ok[idx][hf * 2 + 1]);
            ok[idx][hf * 2] = 0.f; ok[idx][hf * 2 + 1] = 0.f;
        }
}

__global__ __launch_bounds__(ATHR)
void attn_fused(const __nv_bfloat16* __restrict__ QH, const __nv_bfloat16* __restrict__ QL,
                const __nv_bfloat16* __restrict__ KH, const __nv_bfloat16* __restrict__ KL,
                const __nv_bfloat16* __restrict__ ETH, const __nv_bfloat16* __restrict__ ETL,
                const __nv_bfloat16* __restrict__ EH, const __nv_bfloat16* __restrict__ EL,
                const __nv_bfloat16* __restrict__ VTH, const __nv_bfloat16* __restrict__ VTL,
                const float* __restrict__ ACC, const float* __restrict__ P,
                const float* __restrict__ gnw, int* __restrict__ ctr,
                __nv_bfloat16* __restrict__ AH, __nv_bfloat16* __restrict__ AL)
{
    extern __shared__ char sm[];
    const uint32_t sb = smem_to_u32(sm);
    const int tid = threadIdx.x, l = tid & 31, wid = tid >> 5, wm = wid >> 2, wn = wid & 3;

    float ok[8][4];
#pragma unroll
    for (int j = 0; j < 8; j++)
#pragma unroll
        for (int k = 0; k < 4; k++) ok[j][k] = 0.f;

    for (;;) {
        if (tid == 0) *(int*)(sm + SIDX) = atomicAdd(ctr, 1);
        __syncthreads();
        const int widx = *(int*)(sm + SIDX);
        __syncthreads();
        if (widx >= NTILE) break;

        const int qi = 31 - (widx >> 4);
        const int bh = widx & 15;
        const int b = bh >> 2, h = bh & 3;
        const int qBase = qi * 64;
        const size_t base = (size_t)bh * TT * 256;

        ld_xy(sb + QSH, sb + QSL, QH + base + (size_t)qBase * 256,
              QL + base + (size_t)qBase * 256, tid);
        stage_loop(sm, sb, qi, tid, KH + base, KL + base, ETH + base, ETL + base, ok);

        dump_ok(sm, ok, wm, wn, l);
        __syncthreads();
        float* OKS = (float*)(sm + YSH);
#pragma unroll
        for (int i = 0; i < 4; i++) {
            const int r = wid * 4 + i, t = qBase + r;
            float v[8], acr[8], mx = -3.4e38f;
#pragma unroll
            for (int j = 0; j < 8; j++) {
                const int c = j * 32 + l;
                acr[j] = ACC[base + (size_t)t * 256 + c];
                v[j] = OKS[r * 258 + c] / acr[j];
                mx = fmaxf(mx, v[j]);
            }
#pragma unroll
            for (int o = 16; o; o >>= 1) mx = fmaxf(mx, __shfl_xor_sync(~0u, mx, o));
            float e[8], s = 0.f;
#pragma unroll
            for (int j = 0; j < 8; j++) { e[j] = expf(v[j] - mx); s += e[j]; }
#pragma unroll
            for (int o = 16; o; o >>= 1) s += __shfl_xor_sync(~0u, s, o);
            const float inv = 1.f / s;
#pragma unroll
            for (int j = 0; j < 8; j++) {
                const int c = j * 32 + l;
                __nv_bfloat16 hh, ll;
                spl(e[j] * inv / acr[j], hh, ll);
                *(__nv_bfloat16*)(sm + QSH + (r * XSTR + c) * 2) = hh;
                *(__nv_bfloat16*)(sm + QSL + (r * XSTR + c) * 2) = ll;
            }
        }
        __syncthreads();

        stage_loop(sm, sb, qi, tid, EH + base, EL + base, VTH + base, VTL + base, ok);

        dump_ok(sm, ok, wm, wn, l);
        __syncthreads();
#pragma unroll
        for (int i = 0; i < 4; i++) {
            const int r = wid * 4 + i, t = qBase + r;
            float vv[8], ss = 0.f;
#pragma unroll
            for (int j = 0; j < 8; j++) { vv[j] = OKS[r * 258 + j * 32 + l]; ss += vv[j] * vv[j]; }
#pragma unroll
            for (int o = 16; o; o >>= 1) ss += __shfl_xor_sync(~0u, ss, o);
            const float rn = rsqrtf(ss * (1.f / 256.f) + 1e-5f);
#pragma unroll
            for (int j = 0; j < 8; j++) {
                const int c = j * 32 + l;
                float gg = P[(size_t)(b * TT + t) * PD + 3072 + h * 256 + c];
                float sig = 1.f / (1.f + expf(-gg));
                float act = vv[j] * rn * gnw[c] * gg * sig;
                __nv_bfloat16 hh, ll;
                spl(act, hh, ll);
                AH[(size_t)(b * TT + t) * DD + h * 256 + c] = hh;
                AL[(size_t)(b * TT + t) * DD + h * 256 + c] = ll;
            }
        }
        __syncthreads();
    }
}

extern "C" void kernel_launch(void* const* d_in, const int* in_sizes, int n_in,
                              void* d_out, int out_size)
{
    const float* x   = (const float*)d_in[0];
    const float* qw  = (const float*)d_in[1];
    const float* kw  = (const float*)d_in[2];
    const float* vw  = (const float*)d_in[3];
    const float* gw  = (const float*)d_in[4];
    const float* sw  = (const float*)d_in[5];
    const float* sgw = (const float*)d_in[6];
    const float* gnw = (const float*)d_in[7];
    const float* ow  = (const float*)d_in[8];
    float* out = (float*)d_out;

    float *P, *ACC, *XSG, *LAM;
    int* CTR;
    __nv_bfloat16 *XHI, *XLO, *WHI, *WLO, *WOHI, *WOLO, *QHI, *QLO, *KHI, *KLO;
    __nv_bfloat16 *EHI, *ELO, *ETHI, *ETLO, *VTHI, *VTLO;
    cudaGetSymbolAddress((void**)&P, g_P);     cudaGetSymbolAddress((void**)&ACC, g_ACC);
    cudaGetSymbolAddress((void**)&XSG, g_XSG); cudaGetSymbolAddress((void**)&LAM, g_LAM);
    cudaGetSymbolAddress((void**)&CTR, g_ctr);
    cudaGetSymbolAddress((void**)&XHI, g_XHI); cudaGetSymbolAddress((void**)&XLO, g_XLO);
    cudaGetSymbolAddress((void**)&WHI, g_WHI); cudaGetSymbolAddress((void**)&WLO, g_WLO);
    cudaGetSymbolAddress((void**)&WOHI, g_WOHI); cudaGetSymbolAddress((void**)&WOLO, g_WOLO);
    cudaGetSymbolAddress((void**)&QHI, g_QHI); cudaGetSymbolAddress((void**)&QLO, g_QLO);
    cudaGetSymbolAddress((void**)&KHI, g_KHI); cudaGetSymbolAddress((void**)&KLO, g_KLO);
    cudaGetSymbolAddress((void**)&EHI, g_EHI); cudaGetSymbolAddress((void**)&ELO, g_ELO);
    cudaGetSymbolAddress((void**)&ETHI, g_ETHI); cudaGetSymbolAddress((void**)&ETLO, g_ETLO);
    cudaGetSymbolAddress((void**)&VTHI, g_VTHI); cudaGetSymbolAddress((void**)&VTLO, g_VTLO);

    static int done = 0;
    if (!done) {
        cudaFuncSetAttribute(mmagemm, cudaFuncAttributeMaxDynamicSharedMemorySize, GSM_TOTAL);
        cudaFuncSetAttribute(attn_fused, cudaFuncAttributeMaxDynamicSharedMemorySize, ASMEM);
        done = 1;
    }

    // launch order puts attn_fused in ncu slot 6 (-s 5 -c 1)
    splitx_plus<<<9216, 256>>>(x, XHI, XLO, sgw, XSG, CTR);
    wsplit_all<<<dim3(32, 32, 6), 256>>>(qw, kw, vw, gw, sw, ow, WHI, WLO, WOHI, WOLO);
    lam_kernel<<<BH, 256>>>(XSG, LAM);
    mmagemm<<<dim3(PD / 128, BT / 128), 128, GSM_TOTAL>>>(XHI, XLO, WHI, WLO, P, PD);
    prep_all<<<PREP_VT, 256>>>(P, LAM, ACC, EHI, ELO, ETHI, ETLO,
                               QHI, QLO, KHI, KLO, VTHI, VTLO);
    attn_fused<<<148, ATHR, ASMEM>>>(QHI, QLO, KHI, KLO, ETHI, ETLO,
                                     EHI, ELO, VTHI, VTLO, ACC, P, gnw, CTR,
                                     XHI, XLO);
    mmagemm<<<dim3(DD / 128, BT / 128), 128, GSM_TOTAL>>>(XHI, XLO, WOHI, WOLO, out, DD);
}